// round 4
// baseline (speedup 1.0000x reference)
#include <cuda_runtime.h>

// Problem constants
#define IMG_H 512
#define IMG_W 512
#define NIMG  64
#define NPIX  (NIMG * IMG_H * IMG_W)   // 16,777,216

#define TILE_W   32
#define TILE_H   64
#define HALO     5
#define SW_H     74          // TILE_H + 2*HALO
#define SW_W     42          // TILE_W + 2*HALO
#define XY_STRIDE 44         // row stride in float2 units (352B, 16B-aligned)
#define NTHREADS 512
#define GRID_X   (IMG_W / TILE_W)   // 16
#define GRID_Y   (IMG_H / TILE_H)   // 8
#define NBLOCKS  (GRID_X * GRID_Y * NIMG)   // 8192

// SMEM bytes: xy 74*44*8 = 26048 ; midm 74*32*16 = 37888 ; mide 74*32*4 = 9472
#define SMEM_BYTES (26048 + 37888 + 9472)   // 73,408 -> 2 CTAs/SM

// Separable Gaussian (sigma=1.5, 11 taps), normalized. Scalar taps use
// compile-time literals (FFMA-imm form); packed taps use 6 register pairs
// (symmetric kernel).
#define W0 0.00102838f
#define W1 0.00759876f
#define W2 0.03600077f
#define W3 0.10936060f
#define W4 0.21300553f
#define W5 0.26601172f
__device__ constexpr float GW[11] = {W0, W1, W2, W3, W4, W5, W4, W3, W2, W1, W0};
#define GPI(t) ((t) < 6 ? (t) : 10 - (t))

typedef unsigned long long ull;

__device__ __forceinline__ ull pack2(float lo, float hi) {
    ull d;
    asm("mov.b64 %0, {%1, %2};" : "=l"(d) : "r"(__float_as_uint(lo)), "r"(__float_as_uint(hi)));
    return d;
}
__device__ __forceinline__ void unpack2(ull v, float& lo, float& hi) {
    unsigned r0, r1;
    asm("mov.b64 {%0, %1}, %2;" : "=r"(r0), "=r"(r1) : "l"(v));
    lo = __uint_as_float(r0); hi = __uint_as_float(r1);
}
__device__ __forceinline__ ull fma2(ull a, ull b, ull c) {
    ull d;
    asm("fma.rn.f32x2 %0, %1, %2, %3;" : "=l"(d) : "l"(a), "l"(b), "l"(c));
    return d;
}
__device__ __forceinline__ ull mul2(ull a, ull b) {
    ull d;
    asm("mul.rn.f32x2 %0, %1, %2;" : "=l"(d) : "l"(a), "l"(b));
    return d;
}

__device__ float g_partials[NBLOCKS];
__device__ int   g_count = 0;

extern __shared__ char smem_raw[];

__global__ __launch_bounds__(NTHREADS, 2)
void ssim_fused_kernel(const float* __restrict__ img1, const float* __restrict__ img2,
                       float* __restrict__ out) {
    ull*        xy   = (ull*)smem_raw;                         // packed (x,y)
    ulonglong2* midm = (ulonglong2*)(smem_raw + 26048);        // {(mu1,mu2),(sxx,syy)}
    float*      mide = (float*)(smem_raw + 26048 + 37888);     // sxy

    const int tid = threadIdx.x;
    const int img = blockIdx.z;
    const int r0  = blockIdx.y * TILE_H;
    const int c0  = blockIdx.x * TILE_W;
    const float* p1 = img1 + (size_t)img * (IMG_H * IMG_W);
    const float* p2 = img2 + (size_t)img * (IMG_H * IMG_W);

    // Packed Gaussian weight pairs (6 distinct by symmetry)
    ull gp[6];
    gp[0] = pack2(W0, W0); gp[1] = pack2(W1, W1); gp[2] = pack2(W2, W2);
    gp[3] = pack2(W3, W3); gp[4] = pack2(W4, W4); gp[5] = pack2(W5, W5);

    // ---- Load halo tile, interleaved (x,y), zero padding outside image ----
    for (int idx = tid; idx < SW_H * SW_W; idx += NTHREADS) {
        int r = idx / SW_W;
        int c = idx - r * SW_W;
        int gr = r0 + r - HALO;
        int gc = c0 + c - HALO;
        float a = 0.f, b = 0.f;
        if (gr >= 0 && gr < IMG_H && gc >= 0 && gc < IMG_W) {
            int o = gr * IMG_W + gc;
            a = p1[o];
            b = p2[o];
        }
        xy[r * XY_STRIDE + c] = pack2(a, b);
    }
    __syncthreads();

    // ---- Horizontal pass: unit = (row, 4 output cols); 74*8 = 592 units ----
    for (int unit = tid; unit < SW_H * (TILE_W / 4); unit += NTHREADS) {
        int row = unit >> 3;
        int cb  = (unit & 7) * 4;

        ull v[16];
        const ulonglong2* vr = (const ulonglong2*)(xy + row * XY_STRIDE + cb);
        #pragma unroll
        for (int i = 0; i < 8; i++) {
            ulonglong2 t = vr[i];
            v[2 * i]     = t.x;
            v[2 * i + 1] = t.y;
        }

        const int o = row * TILE_W + cb;

        // Sweep A: packed (mu1,mu2) conv + scalar sxy conv
        ull   mu[4]  = {0, 0, 0, 0};
        float sxy[4] = {0, 0, 0, 0};
        #pragma unroll
        for (int k = 0; k < 14; k++) {
            float x, y;
            unpack2(v[k], x, y);
            float e = x * y;
            #pragma unroll
            for (int j = 0; j < 4; j++) {
                int t = k - j;
                if (t >= 0 && t < 11) {
                    mu[j]  = fma2(gp[GPI(t)], v[k], mu[j]);
                    sxy[j] = fmaf(GW[t], e, sxy[j]);
                }
            }
        }
        // Sweep B: packed (sxx,syy) conv
        ull sg[4] = {0, 0, 0, 0};
        #pragma unroll
        for (int k = 0; k < 14; k++) {
            ull p = mul2(v[k], v[k]);
            #pragma unroll
            for (int j = 0; j < 4; j++) {
                int t = k - j;
                if (t >= 0 && t < 11)
                    sg[j] = fma2(gp[GPI(t)], p, sg[j]);
            }
        }
        #pragma unroll
        for (int j = 0; j < 4; j++) {
            midm[o + j] = make_ulonglong2(mu[j], sg[j]);
            mide[o + j] = sxy[j];
        }
    }
    __syncthreads();

    // ---- Vertical pass + SSIM map: col = tid&31, 16 groups x 4 rows ----
    float local = 0.f;
    const int col = tid & (TILE_W - 1);
    const int rb  = (tid >> 5) * 4;

    const float C1 = 0.0001f;
    const float C2 = 0.0009f;

    {
        ull   amu[4] = {0, 0, 0, 0};
        ull   asg[4] = {0, 0, 0, 0};
        float axy[4] = {0, 0, 0, 0};

        #pragma unroll
        for (int k = 0; k < 14; k++) {
            int o = (rb + k) * TILE_W + col;
            ulonglong2 m = midm[o];
            float      e = mide[o];
            #pragma unroll
            for (int j = 0; j < 4; j++) {
                int t = k - j;
                if (t >= 0 && t < 11) {
                    amu[j] = fma2(gp[GPI(t)], m.x, amu[j]);
                    asg[j] = fma2(gp[GPI(t)], m.y, asg[j]);
                    axy[j] = fmaf(GW[t], e, axy[j]);
                }
            }
        }

        #pragma unroll
        for (int j = 0; j < 4; j++) {
            float mu1, mu2, exx, eyy;
            unpack2(amu[j], mu1, mu2);
            unpack2(asg[j], exx, eyy);
            float mu1s = mu1 * mu1;
            float mu2s = mu2 * mu2;
            float mu12 = mu1 * mu2;
            float s1   = exx - mu1s;
            float s2   = eyy - mu2s;
            float s12  = axy[j] - mu12;
            float num  = (2.f * mu12 + C1) * (2.f * s12 + C2);
            float den  = (mu1s + mu2s + C1) * (s1 + s2 + C2);
            local += __fdividef(num, den);
        }
    }

    // ---- Block reduction (fixed order -> deterministic) ----
    #pragma unroll
    for (int off = 16; off > 0; off >>= 1)
        local += __shfl_xor_sync(0xffffffffu, local, off);

    __shared__ float wsum[16];
    __shared__ int   s_last;
    if ((tid & 31) == 0) wsum[tid >> 5] = local;
    __syncthreads();
    if (tid == 0) {
        float s = 0.f;
        #pragma unroll
        for (int w = 0; w < 16; w++) s += wsum[w];
        int bid = (blockIdx.z * gridDim.y + blockIdx.y) * gridDim.x + blockIdx.x;
        g_partials[bid] = s;
        __threadfence();
        int old = atomicAdd(&g_count, 1);
        s_last = (old == NBLOCKS - 1);
    }
    __syncthreads();

    // ---- Last block: deterministic final reduction in fp64, reset counter ----
    if (s_last) {
        __threadfence();
        __shared__ double dsh[16];
        double acc = 0.0;
        #pragma unroll
        for (int i = 0; i < NBLOCKS / NTHREADS; i++)
            acc += (double)g_partials[tid * (NBLOCKS / NTHREADS) + i];
        #pragma unroll
        for (int off = 16; off > 0; off >>= 1)
            acc += __shfl_xor_sync(0xffffffffu, acc, off);
        if ((tid & 31) == 0) dsh[tid >> 5] = acc;
        __syncthreads();
        if (tid == 0) {
            double s = 0.0;
            #pragma unroll
            for (int w = 0; w < 16; w++) s += dsh[w];
            out[0] = (float)(1.0 - s * (1.0 / (double)NPIX));
            g_count = 0;   // reset for next graph replay
        }
    }
}

extern "C" void kernel_launch(void* const* d_in, const int* in_sizes, int n_in,
                              void* d_out, int out_size) {
    const float* pred   = (const float*)d_in[0];
    const float* target = (const float*)d_in[1];
    float* out = (float*)d_out;

    cudaFuncSetAttribute(ssim_fused_kernel,
                         cudaFuncAttributeMaxDynamicSharedMemorySize, SMEM_BYTES);

    dim3 grid(GRID_X, GRID_Y, NIMG);   // (16, 8, 64)
    ssim_fused_kernel<<<grid, NTHREADS, SMEM_BYTES>>>(pred, target, out);
}

// round 5
// speedup vs baseline: 1.2732x; 1.2732x over previous
#include <cuda_runtime.h>

// Problem constants
#define IMG_H 512
#define IMG_W 512
#define NIMG  64
#define NPIX  (NIMG * IMG_H * IMG_W)   // 16,777,216

#define TILE_W   32
#define TILE_H   64
#define HALO     5
#define SW_H     74          // TILE_H + 2*HALO
#define PAD_L    8           // left pad (>= HALO, quad aligned)
#define XY_W     48          // padded strip width in packed elems (12 quads)
#define NTHREADS 640
#define GRID_X   (IMG_W / TILE_W)   // 16
#define GRID_Y   (IMG_H / TILE_H)   // 8
#define NBLOCKS  (GRID_X * GRID_Y * NIMG)   // 8192

// SMEM bytes: xy 74*48*8 = 28416 ; midm 74*32*16 = 37888 ; mide 74*32*4 = 9472
#define XY_BYTES   (SW_H * XY_W * 8)
#define MIDM_BYTES (SW_H * TILE_W * 16)
#define SMEM_BYTES (XY_BYTES + MIDM_BYTES + SW_H * TILE_W * 4)   // 75,776 -> 2 CTAs/SM

// Separable Gaussian (sigma=1.5, 11 taps), normalized.
#define W0 0.00102838f
#define W1 0.00759876f
#define W2 0.03600077f
#define W3 0.10936060f
#define W4 0.21300553f
#define W5 0.26601172f
__device__ constexpr float GW[11] = {W0, W1, W2, W3, W4, W5, W4, W3, W2, W1, W0};
#define GPI(t) ((t) < 6 ? (t) : 10 - (t))

typedef unsigned long long ull;

__device__ __forceinline__ ull pack2(float lo, float hi) {
    ull d;
    asm("mov.b64 %0, {%1, %2};" : "=l"(d) : "r"(__float_as_uint(lo)), "r"(__float_as_uint(hi)));
    return d;
}
__device__ __forceinline__ void unpack2(ull v, float& lo, float& hi) {
    unsigned r0, r1;
    asm("mov.b64 {%0, %1}, %2;" : "=r"(r0), "=r"(r1) : "l"(v));
    lo = __uint_as_float(r0); hi = __uint_as_float(r1);
}
__device__ __forceinline__ ull fma2(ull a, ull b, ull c) {
    ull d;
    asm("fma.rn.f32x2 %0, %1, %2, %3;" : "=l"(d) : "l"(a), "l"(b), "l"(c));
    return d;
}
__device__ __forceinline__ ull mul2(ull a, ull b) {
    ull d;
    asm("mul.rn.f32x2 %0, %1, %2;" : "=l"(d) : "l"(a), "l"(b));
    return d;
}

__device__ float g_partials[NBLOCKS];
__device__ int   g_count = 0;

extern __shared__ char smem_raw[];

__global__ __launch_bounds__(NTHREADS, 2)
void ssim_fused_kernel(const float* __restrict__ img1, const float* __restrict__ img2,
                       float* __restrict__ out) {
    ull*        xy   = (ull*)smem_raw;                               // packed (x,y), 74x48
    ulonglong2* midm = (ulonglong2*)(smem_raw + XY_BYTES);           // {(mu1,mu2),(sxx,syy)}
    float*      mide = (float*)(smem_raw + XY_BYTES + MIDM_BYTES);   // sxy

    const int tid = threadIdx.x;
    const int img = blockIdx.z;
    const int r0  = blockIdx.y * TILE_H;
    const int c0  = blockIdx.x * TILE_W;
    const float* p1 = img1 + (size_t)img * (IMG_H * IMG_W);
    const float* p2 = img2 + (size_t)img * (IMG_H * IMG_W);

    // Packed Gaussian weight pairs (6 distinct by symmetry)
    ull gp[6];
    gp[0] = pack2(W0, W0); gp[1] = pack2(W1, W1); gp[2] = pack2(W2, W2);
    gp[3] = pack2(W3, W3); gp[4] = pack2(W4, W4); gp[5] = pack2(W5, W5);

    // ---- Load halo strip: unit = (row, quad of 4 cols), both images ----
    // Strip covers global cols [c0-8, c0+40). Every quad is uniformly valid or
    // uniformly OOB in x (c0 % 32 == 0, quads 4-aligned), so one predicate/quad.
    for (int u = tid; u < SW_H * (XY_W / 4); u += NTHREADS) {
        int r = u / (XY_W / 4);          // 0..73
        int q = u - r * (XY_W / 4);      // 0..11
        int gr = r0 + r - HALO;
        int gc = c0 - PAD_L + q * 4;
        float4 vx = make_float4(0.f, 0.f, 0.f, 0.f);
        float4 vy = vx;
        if (gr >= 0 && gr < IMG_H && gc >= 0 && gc + 3 < IMG_W) {
            const float4* a4 = (const float4*)(p1 + (size_t)gr * IMG_W + gc);
            const float4* b4 = (const float4*)(p2 + (size_t)gr * IMG_W + gc);
            vx = *a4;
            vy = *b4;
        }
        ulonglong2* dst = (ulonglong2*)(xy + r * XY_W + q * 4);
        dst[0] = make_ulonglong2(pack2(vx.x, vy.x), pack2(vx.y, vy.y));
        dst[1] = make_ulonglong2(pack2(vx.z, vy.z), pack2(vx.w, vy.w));
    }
    __syncthreads();

    // ---- Horizontal pass: unit = (row, 4 output cols); 74*8 = 592 units, 1 round ----
    for (int unit = tid; unit < SW_H * (TILE_W / 4); unit += NTHREADS) {
        int row = unit >> 3;
        int cb  = (unit & 7) * 4;

        // Output col cb+j needs input cols (needed coords) cb+j..cb+j+10;
        // needed col n lives at smem col n + (PAD_L - HALO) = n + 3.
        // Load 16 packed values starting at smem col cb+2 (16B aligned); use v[1..14].
        ull v[16];
        const ulonglong2* vr = (const ulonglong2*)(xy + row * XY_W + cb + 2);
        #pragma unroll
        for (int i = 0; i < 8; i++) {
            ulonglong2 t = vr[i];
            v[2 * i]     = t.x;
            v[2 * i + 1] = t.y;
        }

        const int o = row * TILE_W + cb;

        // Sweep A: packed (mu1,mu2) conv + scalar sxy conv
        ull   mu[4]  = {0, 0, 0, 0};
        float sxy[4] = {0, 0, 0, 0};
        #pragma unroll
        for (int k = 1; k < 15; k++) {
            float x, y;
            unpack2(v[k], x, y);
            float e = x * y;
            #pragma unroll
            for (int j = 0; j < 4; j++) {
                int t = k - 1 - j;
                if (t >= 0 && t < 11) {
                    mu[j]  = fma2(gp[GPI(t)], v[k], mu[j]);
                    sxy[j] = fmaf(GW[t], e, sxy[j]);
                }
            }
        }
        // Sweep B: packed (sxx,syy) conv
        ull sg[4] = {0, 0, 0, 0};
        #pragma unroll
        for (int k = 1; k < 15; k++) {
            ull p = mul2(v[k], v[k]);
            #pragma unroll
            for (int j = 0; j < 4; j++) {
                int t = k - 1 - j;
                if (t >= 0 && t < 11)
                    sg[j] = fma2(gp[GPI(t)], p, sg[j]);
            }
        }
        #pragma unroll
        for (int j = 0; j < 4; j++) {
            midm[o + j] = make_ulonglong2(mu[j], sg[j]);
            mide[o + j] = sxy[j];
        }
    }
    __syncthreads();

    // ---- Vertical pass + SSIM map: 16 groups x 32 cols, 4 rows each ----
    float local = 0.f;
    const int col = tid & (TILE_W - 1);
    const int grp = tid >> 5;

    const float C1 = 0.0001f;
    const float C2 = 0.0009f;

    if (grp < 16) {
        const int rb = grp * 4;
        ull   amu[4] = {0, 0, 0, 0};
        ull   asg[4] = {0, 0, 0, 0};
        float axy[4] = {0, 0, 0, 0};

        #pragma unroll
        for (int k = 0; k < 14; k++) {
            int o = (rb + k) * TILE_W + col;
            ulonglong2 m = midm[o];
            float      e = mide[o];
            #pragma unroll
            for (int j = 0; j < 4; j++) {
                int t = k - j;
                if (t >= 0 && t < 11) {
                    amu[j] = fma2(gp[GPI(t)], m.x, amu[j]);
                    asg[j] = fma2(gp[GPI(t)], m.y, asg[j]);
                    axy[j] = fmaf(GW[t], e, axy[j]);
                }
            }
        }

        #pragma unroll
        for (int j = 0; j < 4; j++) {
            float mu1, mu2, exx, eyy;
            unpack2(amu[j], mu1, mu2);
            unpack2(asg[j], exx, eyy);
            float mu1s = mu1 * mu1;
            float mu2s = mu2 * mu2;
            float mu12 = mu1 * mu2;
            float s1   = exx - mu1s;
            float s2   = eyy - mu2s;
            float s12  = axy[j] - mu12;
            float num  = (2.f * mu12 + C1) * (2.f * s12 + C2);
            float den  = (mu1s + mu2s + C1) * (s1 + s2 + C2);
            local += __fdividef(num, den);
        }
    }

    // ---- Block reduction (fixed order -> deterministic) ----
    #pragma unroll
    for (int off = 16; off > 0; off >>= 1)
        local += __shfl_xor_sync(0xffffffffu, local, off);

    __shared__ float wsum[NTHREADS / 32];
    __shared__ int   s_last;
    if ((tid & 31) == 0) wsum[tid >> 5] = local;
    __syncthreads();
    if (tid == 0) {
        float s = 0.f;
        #pragma unroll
        for (int w = 0; w < NTHREADS / 32; w++) s += wsum[w];
        int bid = (blockIdx.z * gridDim.y + blockIdx.y) * gridDim.x + blockIdx.x;
        g_partials[bid] = s;
        __threadfence();
        int old = atomicAdd(&g_count, 1);
        s_last = (old == NBLOCKS - 1);
    }
    __syncthreads();

    // ---- Last block: deterministic final reduction in fp64, reset counter ----
    if (s_last) {
        __threadfence();
        __shared__ double dsh[NTHREADS / 32];
        double acc = 0.0;
        const int per = (NBLOCKS + NTHREADS - 1) / NTHREADS;   // 13
        #pragma unroll
        for (int i = 0; i < per; i++) {
            int idx = tid * per + i;
            if (idx < NBLOCKS) acc += (double)g_partials[idx];
        }
        #pragma unroll
        for (int off = 16; off > 0; off >>= 1)
            acc += __shfl_xor_sync(0xffffffffu, acc, off);
        if ((tid & 31) == 0) dsh[tid >> 5] = acc;
        __syncthreads();
        if (tid == 0) {
            double s = 0.0;
            #pragma unroll
            for (int w = 0; w < NTHREADS / 32; w++) s += dsh[w];
            out[0] = (float)(1.0 - s * (1.0 / (double)NPIX));
            g_count = 0;   // reset for next graph replay
        }
    }
}

extern "C" void kernel_launch(void* const* d_in, const int* in_sizes, int n_in,
                              void* d_out, int out_size) {
    const float* pred   = (const float*)d_in[0];
    const float* target = (const float*)d_in[1];
    float* out = (float*)d_out;

    cudaFuncSetAttribute(ssim_fused_kernel,
                         cudaFuncAttributeMaxDynamicSharedMemorySize, SMEM_BYTES);

    dim3 grid(GRID_X, GRID_Y, NIMG);   // (16, 8, 64)
    ssim_fused_kernel<<<grid, NTHREADS, SMEM_BYTES>>>(pred, target, out);
}

// round 7
// speedup vs baseline: 1.3956x; 1.0961x over previous
#include <cuda_runtime.h>

// Problem constants
#define IMG_H 512
#define IMG_W 512
#define NIMG  64
#define NPIX  (NIMG * IMG_H * IMG_W)   // 16,777,216

#define TILE_W   32
#define TILE_H   64
#define HALO     5
#define SW_H     74          // TILE_H + 2*HALO
#define PAD_L    8           // left pad (>= HALO, quad aligned)
#define XY_W     48          // padded strip width in packed elems (12 quads)
#define NTHREADS 512
#define GRID_X   (IMG_W / TILE_W)   // 16
#define GRID_Y   (IMG_H / TILE_H)   // 8
#define NBLOCKS  (GRID_X * GRID_Y * NIMG)   // 8192

// SMEM bytes: xy 74*48*8 = 28416 ; midm 74*32*16 = 37888 ; mide 74*32*4 = 9472
#define XY_BYTES   (SW_H * XY_W * 8)
#define MIDM_BYTES (SW_H * TILE_W * 16)
#define SMEM_BYTES (XY_BYTES + MIDM_BYTES + SW_H * TILE_W * 4)   // 75,776 -> 3 CTAs/SM

// Separable Gaussian (sigma=1.5, 11 taps), normalized.
#define W0 0.00102838f
#define W1 0.00759876f
#define W2 0.03600077f
#define W3 0.10936060f
#define W4 0.21300553f
#define W5 0.26601172f
__device__ constexpr float GW[11] = {W0, W1, W2, W3, W4, W5, W4, W3, W2, W1, W0};
#define GPI(t) ((t) < 6 ? (t) : 10 - (t))

typedef unsigned long long ull;

__device__ __forceinline__ ull pack2(float lo, float hi) {
    ull d;
    asm("mov.b64 %0, {%1, %2};" : "=l"(d) : "r"(__float_as_uint(lo)), "r"(__float_as_uint(hi)));
    return d;
}
__device__ __forceinline__ void unpack2(ull v, float& lo, float& hi) {
    unsigned r0, r1;
    asm("mov.b64 {%0, %1}, %2;" : "=r"(r0), "=r"(r1) : "l"(v));
    lo = __uint_as_float(r0); hi = __uint_as_float(r1);
}
__device__ __forceinline__ ull fma2(ull a, ull b, ull c) {
    ull d;
    asm("fma.rn.f32x2 %0, %1, %2, %3;" : "=l"(d) : "l"(a), "l"(b), "l"(c));
    return d;
}
__device__ __forceinline__ ull mul2(ull a, ull b) {
    ull d;
    asm("mul.rn.f32x2 %0, %1, %2;" : "=l"(d) : "l"(a), "l"(b));
    return d;
}

__device__ float g_partials[NBLOCKS];
__device__ int   g_count = 0;

extern __shared__ char smem_raw[];

__global__ __launch_bounds__(NTHREADS, 3)
void ssim_fused_kernel(const float* __restrict__ img1, const float* __restrict__ img2,
                       float* __restrict__ out) {
    ull*        xy   = (ull*)smem_raw;                               // packed (x,y), 74x48
    ulonglong2* midm = (ulonglong2*)(smem_raw + XY_BYTES);           // {(mu1,mu2),(sxx,syy)}
    float*      mide = (float*)(smem_raw + XY_BYTES + MIDM_BYTES);   // sxy

    const int tid = threadIdx.x;
    const int img = blockIdx.z;
    const int r0  = blockIdx.y * TILE_H;
    const int c0  = blockIdx.x * TILE_W;
    const float* p1 = img1 + (size_t)img * (IMG_H * IMG_W);
    const float* p2 = img2 + (size_t)img * (IMG_H * IMG_W);

    // Packed Gaussian weight pairs (6 distinct by symmetry)
    ull gp[6];
    gp[0] = pack2(W0, W0); gp[1] = pack2(W1, W1); gp[2] = pack2(W2, W2);
    gp[3] = pack2(W3, W3); gp[4] = pack2(W4, W4); gp[5] = pack2(W5, W5);

    // ---- Load halo strip: unit = (row, quad of 4 cols), both images ----
    // Strip covers global cols [c0-8, c0+40). Every quad is uniformly valid or
    // uniformly OOB (c0 % 32 == 0, quads 4-aligned), so one predicate/quad.
    for (int u = tid; u < SW_H * (XY_W / 4); u += NTHREADS) {
        int r = u / (XY_W / 4);          // 0..73
        int q = u - r * (XY_W / 4);      // 0..11
        int gr = r0 + r - HALO;
        int gc = c0 - PAD_L + q * 4;
        float4 vx = make_float4(0.f, 0.f, 0.f, 0.f);
        float4 vy = vx;
        if (gr >= 0 && gr < IMG_H && gc >= 0 && gc + 3 < IMG_W) {
            const float4* a4 = (const float4*)(p1 + (size_t)gr * IMG_W + gc);
            const float4* b4 = (const float4*)(p2 + (size_t)gr * IMG_W + gc);
            vx = *a4;
            vy = *b4;
        }
        ulonglong2* dst = (ulonglong2*)(xy + r * XY_W + q * 4);
        dst[0] = make_ulonglong2(pack2(vx.x, vy.x), pack2(vx.y, vy.y));
        dst[1] = make_ulonglong2(pack2(vx.z, vy.z), pack2(vx.w, vy.w));
    }
    __syncthreads();

    // ---- Horizontal pass: unit = (row, 4 output cols); 74*8 = 592 units ----
    for (int unit = tid; unit < SW_H * (TILE_W / 4); unit += NTHREADS) {
        int row = unit >> 3;
        int cb  = (unit & 7) * 4;

        // Needed input col n lives at smem col n + (PAD_L - HALO) = n + 3.
        // Load 16 packed starting at smem col cb+2 (16B aligned); use v[1..14].
        ull v[16];
        const ulonglong2* vr = (const ulonglong2*)(xy + row * XY_W + cb + 2);
        #pragma unroll
        for (int i = 0; i < 8; i++) {
            ulonglong2 t = vr[i];
            v[2 * i]     = t.x;
            v[2 * i + 1] = t.y;
        }

        const int o = row * TILE_W + cb;

        // Sweep A: packed (mu1,mu2) conv + scalar sxy conv
        ull   mu[4]  = {0, 0, 0, 0};
        float sxy[4] = {0, 0, 0, 0};
        #pragma unroll
        for (int k = 1; k < 15; k++) {
            float x, y;
            unpack2(v[k], x, y);
            float e = x * y;
            #pragma unroll
            for (int j = 0; j < 4; j++) {
                const int t = k - 1 - j;
                if (t >= 0 && t < 11) {
                    const ull  gpt = gp[GPI(t)];
                    mu[j]  = fma2(gpt, v[k], mu[j]);
                    sxy[j] = fmaf(GW[t], e, sxy[j]);
                }
            }
        }
        // Sweep B: packed (sxx,syy) conv
        ull sg[4] = {0, 0, 0, 0};
        #pragma unroll
        for (int k = 1; k < 15; k++) {
            ull p = mul2(v[k], v[k]);
            #pragma unroll
            for (int j = 0; j < 4; j++) {
                const int t = k - 1 - j;
                if (t >= 0 && t < 11)
                    sg[j] = fma2(gp[GPI(t)], p, sg[j]);
            }
        }
        #pragma unroll
        for (int j = 0; j < 4; j++) {
            midm[o + j] = make_ulonglong2(mu[j], sg[j]);
            mide[o + j] = sxy[j];
        }
    }
    __syncthreads();

    // ---- Vertical pass + SSIM map: 16 groups x 32 cols, 4 rows each ----
    float local = 0.f;
    const int col = tid & (TILE_W - 1);
    const int rb  = (tid >> 5) * 4;

    const float C1 = 0.0001f;
    const float C2 = 0.0009f;

    {
        ull   amu[4] = {0, 0, 0, 0};
        ull   asg[4] = {0, 0, 0, 0};
        float axy[4] = {0, 0, 0, 0};

        #pragma unroll
        for (int k = 0; k < 14; k++) {
            int o = (rb + k) * TILE_W + col;
            ulonglong2 m = midm[o];
            float      e = mide[o];
            #pragma unroll
            for (int j = 0; j < 4; j++) {
                const int t = k - j;
                if (t >= 0 && t < 11) {
                    const ull gpt = gp[GPI(t)];
                    amu[j] = fma2(gpt, m.x, amu[j]);
                    asg[j] = fma2(gpt, m.y, asg[j]);
                    axy[j] = fmaf(GW[t], e, axy[j]);
                }
            }
        }

        #pragma unroll
        for (int j = 0; j < 4; j++) {
            float mu1, mu2, exx, eyy;
            unpack2(amu[j], mu1, mu2);
            unpack2(asg[j], exx, eyy);
            float mu1s = mu1 * mu1;
            float mu2s = mu2 * mu2;
            float mu12 = mu1 * mu2;
            float s1   = exx - mu1s;
            float s2   = eyy - mu2s;
            float s12  = axy[j] - mu12;
            float num  = (2.f * mu12 + C1) * (2.f * s12 + C2);
            float den  = (mu1s + mu2s + C1) * (s1 + s2 + C2);
            local += __fdividef(num, den);
        }
    }

    // ---- Block reduction (fixed order -> deterministic) ----
    #pragma unroll
    for (int off = 16; off > 0; off >>= 1)
        local += __shfl_xor_sync(0xffffffffu, local, off);

    __shared__ float wsum[NTHREADS / 32];
    __shared__ int   s_last;
    if ((tid & 31) == 0) wsum[tid >> 5] = local;
    __syncthreads();
    if (tid == 0) {
        float s = 0.f;
        #pragma unroll
        for (int w = 0; w < NTHREADS / 32; w++) s += wsum[w];
        int bid = (blockIdx.z * gridDim.y + blockIdx.y) * gridDim.x + blockIdx.x;
        g_partials[bid] = s;
        __threadfence();
        int old = atomicAdd(&g_count, 1);
        s_last = (old == NBLOCKS - 1);
    }
    __syncthreads();

    // ---- Last block: deterministic final reduction in fp64, reset counter ----
    if (s_last) {
        __threadfence();
        __shared__ double dsh[NTHREADS / 32];
        double acc = 0.0;
        const int per = NBLOCKS / NTHREADS;   // 16
        for (int i = 0; i < per; i++)
            acc += (double)g_partials[tid * per + i];
        #pragma unroll
        for (int off = 16; off > 0; off >>= 1)
            acc += __shfl_xor_sync(0xffffffffu, acc, off);
        if ((tid & 31) == 0) dsh[tid >> 5] = acc;
        __syncthreads();
        if (tid == 0) {
            double s = 0.0;
            #pragma unroll
            for (int w = 0; w < NTHREADS / 32; w++) s += dsh[w];
            out[0] = (float)(1.0 - s * (1.0 / (double)NPIX));
            g_count = 0;   // reset for next graph replay
        }
    }
}

extern "C" void kernel_launch(void* const* d_in, const int* in_sizes, int n_in,
                              void* d_out, int out_size) {
    const float* pred   = (const float*)d_in[0];
    const float* target = (const float*)d_in[1];
    float* out = (float*)d_out;

    cudaFuncSetAttribute(ssim_fused_kernel,
                         cudaFuncAttributeMaxDynamicSharedMemorySize, SMEM_BYTES);

    dim3 grid(GRID_X, GRID_Y, NIMG);   // (16, 8, 64)
    ssim_fused_kernel<<<grid, NTHREADS, SMEM_BYTES>>>(pred, target, out);
}